// round 1
// baseline (speedup 1.0000x reference)
#include <cuda_runtime.h>
#include <cuda_bf16.h>

// Problem constants
#define BB 4
#define SS 2048
#define DD 512
#define HH 8
#define DK 64
#define DV 64
#define BS (BB * SS)          // 8192 rows total
#define QTROWS 32             // query rows per attention block
#define NQT (SS / QTROWS)     // 64 q-tiles per batch

// Scratch (device globals: no allocations allowed)
__device__ float g_q[BS * DK];
__device__ float g_k[BS * DK];
__device__ float g_v[BS * DV];
__device__ float g_o[BS * DV];
__device__ float g_woeff[DV * DD];   // 64 x 512

// ---------------------------------------------------------------------------
// Kernel 1: fold Wo over identical heads: woeff[r,c] = sum_h Wo[h*64+r, c]
// ---------------------------------------------------------------------------
__global__ void woeff_kernel(const float* __restrict__ Wo) {
    int idx = blockIdx.x * blockDim.x + threadIdx.x;   // 64*512 = 32768
    if (idx < DV * DD) {
        int r = idx >> 9;          // /512
        int c = idx & 511;
        float s = 0.f;
#pragma unroll
        for (int h = 0; h < HH; ++h) s += Wo[((h << 6) + r) * DD + c];
        g_woeff[idx] = s;
    }
}

// ---------------------------------------------------------------------------
// Kernel 2: fused projections.  blockIdx.y: 0->q(query,Wq) 1->k(key,Wk) 2->v(key,Wv)
// C[8192,64] = A[8192,512] @ W[512,64] + b
// BM=64, BN=64, BK=32, 256 threads, 4x4 micro-tile.
// ---------------------------------------------------------------------------
__global__ void __launch_bounds__(256) proj_kernel(
    const float* __restrict__ query, const float* __restrict__ key,
    const float* __restrict__ Wq, const float* __restrict__ bq,
    const float* __restrict__ Wk, const float* __restrict__ bk,
    const float* __restrict__ Wv, const float* __restrict__ bv)
{
    const int which = blockIdx.y;
    const float* A    = (which == 0) ? query : key;
    const float* W    = (which == 0) ? Wq : (which == 1) ? Wk : Wv;
    const float* bias = (which == 0) ? bq : (which == 1) ? bk : bv;
    float* outp       = (which == 0) ? g_q : (which == 1) ? g_k : g_v;

    const int m0 = blockIdx.x * 64;
    __shared__ float As[64][33];   // padded: avoid conflicts on a-reads
    __shared__ float Ws[32][64];

    const int t  = threadIdx.x;
    const int tr = t >> 4;         // 0..15 (4 rows each)
    const int tc = t & 15;         // 0..15 (4 cols each)

    float acc[4][4] = {};

    for (int kk = 0; kk < DD; kk += 32) {
        __syncthreads();
        // load A tile 64x32 (512 float4, 2 per thread)
#pragma unroll
        for (int u = 0; u < 2; ++u) {
            int fi = t + u * 256;
            int r  = fi >> 3;
            int c4 = (fi & 7) << 2;
            float4 a4 = *(const float4*)(A + (size_t)(m0 + r) * DD + kk + c4);
            As[r][c4 + 0] = a4.x; As[r][c4 + 1] = a4.y;
            As[r][c4 + 2] = a4.z; As[r][c4 + 3] = a4.w;
        }
        // load W tile 32x64 (512 float4, 2 per thread)
#pragma unroll
        for (int u = 0; u < 2; ++u) {
            int fi = t + u * 256;
            int r  = fi >> 4;
            int c4 = (fi & 15) << 2;
            *(float4*)&Ws[r][c4] = *(const float4*)(W + (size_t)(kk + r) * DK + c4);
        }
        __syncthreads();

#pragma unroll 8
        for (int k = 0; k < 32; ++k) {
            float a0 = As[(tr << 2) + 0][k];
            float a1 = As[(tr << 2) + 1][k];
            float a2 = As[(tr << 2) + 2][k];
            float a3 = As[(tr << 2) + 3][k];
            float4 b4 = *(const float4*)&Ws[k][tc << 2];
            acc[0][0] += a0 * b4.x; acc[0][1] += a0 * b4.y; acc[0][2] += a0 * b4.z; acc[0][3] += a0 * b4.w;
            acc[1][0] += a1 * b4.x; acc[1][1] += a1 * b4.y; acc[1][2] += a1 * b4.z; acc[1][3] += a1 * b4.w;
            acc[2][0] += a2 * b4.x; acc[2][1] += a2 * b4.y; acc[2][2] += a2 * b4.z; acc[2][3] += a2 * b4.w;
            acc[3][0] += a3 * b4.x; acc[3][1] += a3 * b4.y; acc[3][2] += a3 * b4.z; acc[3][3] += a3 * b4.w;
        }
    }

    float4 bb = *(const float4*)(bias + (tc << 2));
#pragma unroll
    for (int i = 0; i < 4; ++i) {
        float4 r4 = make_float4(acc[i][0] + bb.x, acc[i][1] + bb.y,
                                acc[i][2] + bb.z, acc[i][3] + bb.w);
        *(float4*)(outp + (size_t)(m0 + (tr << 2) + i) * DK + (tc << 2)) = r4;
    }
}

// ---------------------------------------------------------------------------
// Kernel 3: causal flash attention (one head).
// Block = one 32-row query tile of one batch. 256 threads = 8 warps.
// Warp w owns q-rows [4w, 4w+4); lane owns S-cols {2*lane, 2*lane+1}.
// Online softmax; KV tiles of 64 rows.
// ---------------------------------------------------------------------------
__global__ void __launch_bounds__(256) attn_kernel() {
    // longest-first scheduling, batches interleaved
    const int b   = blockIdx.x & 3;
    const int it  = (NQT - 1) - (blockIdx.x >> 2);

    __shared__ float qT[64][32];      // [d][r]
    __shared__ float kT[64][66];      // [d][c]; reused as pT[64][34]
    __shared__ float sv[64][64];      // [c][d]

    const int t  = threadIdx.x;
    const int tr = t >> 5;            // warp id = row group (all lanes same tr)
    const int tc = t & 31;            // lane

    // load q tile (32x64) transposed into qT
    const float* qg = g_q + (size_t)(b * SS + it * QTROWS) * DK;
#pragma unroll
    for (int u = 0; u < 2; ++u) {
        int fi = t + u * 256;         // 512 float4
        int r  = fi >> 4;             // 0..31
        int c4 = (fi & 15) << 2;
        float4 v4 = *(const float4*)(qg + r * DK + c4);
        qT[c4 + 0][r] = v4.x; qT[c4 + 1][r] = v4.y;
        qT[c4 + 2][r] = v4.z; qT[c4 + 3][r] = v4.w;
    }

    float acc[4][2] = {};
    float mrow[4], lrow[4];
#pragma unroll
    for (int i = 0; i < 4; ++i) { mrow[i] = -1e30f; lrow[i] = 0.f; }

    const int lastpos = it * QTROWS + QTROWS - 1;
    const int ntiles  = (lastpos >> 6) + 1;
    const float* kg = g_k + (size_t)(b * SS) * DK;
    const float* vg = g_v + (size_t)(b * SS) * DK;

    for (int jt = 0; jt < ntiles; ++jt) {
        __syncthreads();   // previous iter's pT/sv readers done
        // load k (transposed) and v tiles, 64x64 each
#pragma unroll
        for (int u = 0; u < 4; ++u) {
            int fi = t + u * 256;     // 1024 float4
            int r  = fi >> 4;
            int c4 = (fi & 15) << 2;
            float4 a4 = *(const float4*)(kg + (size_t)(jt * 64 + r) * DK + c4);
            kT[c4 + 0][r] = a4.x; kT[c4 + 1][r] = a4.y;
            kT[c4 + 2][r] = a4.z; kT[c4 + 3][r] = a4.w;
            float4 w4 = *(const float4*)(vg + (size_t)(jt * 64 + r) * DK + c4);
            *(float4*)&sv[r][c4] = w4;
        }
        __syncthreads();

        // S = q k^T for this tile
        float s[4][2] = {};
#pragma unroll 16
        for (int d = 0; d < 64; ++d) {
            float4 q4 = *(const float4*)&qT[d][tr << 2];
            float2 k2 = *(const float2*)&kT[d][tc << 1];
            s[0][0] += q4.x * k2.x; s[0][1] += q4.x * k2.y;
            s[1][0] += q4.y * k2.x; s[1][1] += q4.y * k2.y;
            s[2][0] += q4.z * k2.x; s[2][1] += q4.z * k2.y;
            s[3][0] += q4.w * k2.x; s[3][1] += q4.w * k2.y;
        }

        // scale + causal mask (only last tile can be partially masked)
        const bool maskTile = (jt == ntiles - 1);
#pragma unroll
        for (int i = 0; i < 4; ++i) {
            int qpos = it * QTROWS + (tr << 2) + i;
#pragma unroll
            for (int j = 0; j < 2; ++j) {
                float v = s[i][j] * 0.125f;
                int kpos = (jt << 6) + (tc << 1) + j;
                if (maskTile && kpos > qpos) v = -1e30f;
                s[i][j] = v;
            }
        }

        // online softmax per row (full-warp reduce; warp == row group)
#pragma unroll
        for (int i = 0; i < 4; ++i) {
            float rm = fmaxf(s[i][0], s[i][1]);
#pragma unroll
            for (int off = 16; off; off >>= 1)
                rm = fmaxf(rm, __shfl_xor_sync(0xffffffffu, rm, off));
            float nm = fmaxf(mrow[i], rm);
            float p0 = __expf(s[i][0] - nm);
            float p1 = __expf(s[i][1] - nm);
            float rs = p0 + p1;
#pragma unroll
            for (int off = 16; off; off >>= 1)
                rs += __shfl_xor_sync(0xffffffffu, rs, off);
            float corr = __expf(mrow[i] - nm);
            lrow[i] = lrow[i] * corr + rs;
            mrow[i] = nm;
            acc[i][0] *= corr; acc[i][1] *= corr;
            s[i][0] = p0; s[i][1] = p1;
        }

        __syncthreads();   // all S-phase reads of kT complete
        // store P transposed into kT region: pT[c][r], pitch 34
        float* pT = &kT[0][0];
#pragma unroll
        for (int j = 0; j < 2; ++j) {
            int c = (tc << 1) + j;
            float2 w0 = make_float2(s[0][j], s[1][j]);
            float2 w1 = make_float2(s[2][j], s[3][j]);
            *(float2*)&pT[c * 34 + (tr << 2) + 0] = w0;
            *(float2*)&pT[c * 34 + (tr << 2) + 2] = w1;
        }
        __syncthreads();

        // PV: acc[i][j] += p[r_i][c] * v[c][d_j]
#pragma unroll 8
        for (int c = 0; c < 64; ++c) {
            float2 pa = *(const float2*)&pT[c * 34 + (tr << 2)];
            float2 pb = *(const float2*)&pT[c * 34 + (tr << 2) + 2];
            float2 v2 = *(const float2*)&sv[c][tc << 1];
            acc[0][0] += pa.x * v2.x; acc[0][1] += pa.x * v2.y;
            acc[1][0] += pa.y * v2.x; acc[1][1] += pa.y * v2.y;
            acc[2][0] += pb.x * v2.x; acc[2][1] += pb.x * v2.y;
            acc[3][0] += pb.y * v2.x; acc[3][1] += pb.y * v2.y;
        }
    }

    // finalize: o = acc / l
    float* og = g_o + (size_t)(b * SS + it * QTROWS) * DV;
#pragma unroll
    for (int i = 0; i < 4; ++i) {
        float inv = 1.0f / lrow[i];
        float2 r2 = make_float2(acc[i][0] * inv, acc[i][1] * inv);
        *(float2*)(og + ((tr << 2) + i) * DV + (tc << 1)) = r2;
    }
}

// ---------------------------------------------------------------------------
// Kernel 4: out[8192,512] = o[8192,64] @ woeff[64,512] + bo
// BM=64, BN=64, K=64 (single pass). 256 threads, 4x4 micro-tile.
// ---------------------------------------------------------------------------
__global__ void __launch_bounds__(256) outgemm_kernel(
    const float* __restrict__ bo, float* __restrict__ out)
{
    const int m0 = blockIdx.x * 64;
    const int n0 = blockIdx.y * 64;
    __shared__ float Ao[64][65];
    __shared__ float Wt[64][64];

    const int t  = threadIdx.x;
    const int tr = t >> 4;
    const int tc = t & 15;

#pragma unroll
    for (int u = 0; u < 4; ++u) {
        int fi = t + u * 256;          // 1024 float4 each
        int r  = fi >> 4;
        int c4 = (fi & 15) << 2;
        float4 a4 = *(const float4*)(g_o + (size_t)(m0 + r) * DV + c4);
        Ao[r][c4 + 0] = a4.x; Ao[r][c4 + 1] = a4.y;
        Ao[r][c4 + 2] = a4.z; Ao[r][c4 + 3] = a4.w;
        *(float4*)&Wt[r][c4] = *(const float4*)(g_woeff + (size_t)r * DD + n0 + c4);
    }
    __syncthreads();

    float acc[4][4] = {};
#pragma unroll 8
    for (int k = 0; k < 64; ++k) {
        float a0 = Ao[(tr << 2) + 0][k];
        float a1 = Ao[(tr << 2) + 1][k];
        float a2 = Ao[(tr << 2) + 2][k];
        float a3 = Ao[(tr << 2) + 3][k];
        float4 b4 = *(const float4*)&Wt[k][tc << 2];
        acc[0][0] += a0 * b4.x; acc[0][1] += a0 * b4.y; acc[0][2] += a0 * b4.z; acc[0][3] += a0 * b4.w;
        acc[1][0] += a1 * b4.x; acc[1][1] += a1 * b4.y; acc[1][2] += a1 * b4.z; acc[1][3] += a1 * b4.w;
        acc[2][0] += a2 * b4.x; acc[2][1] += a2 * b4.y; acc[2][2] += a2 * b4.z; acc[2][3] += a2 * b4.w;
        acc[3][0] += a3 * b4.x; acc[3][1] += a3 * b4.y; acc[3][2] += a3 * b4.z; acc[3][3] += a3 * b4.w;
    }

    float4 bb = *(const float4*)(bo + n0 + (tc << 2));
#pragma unroll
    for (int i = 0; i < 4; ++i) {
        float4 r4 = make_float4(acc[i][0] + bb.x, acc[i][1] + bb.y,
                                acc[i][2] + bb.z, acc[i][3] + bb.w);
        *(float4*)(out + (size_t)(m0 + (tr << 2) + i) * DD + n0 + (tc << 2)) = r4;
    }
}

// ---------------------------------------------------------------------------
// Launch
// Inputs: 0 query, 1 key, 2 value(unused), 3 Wq, 4 bq, 5 Wk, 6 bk,
//         7 Wv, 8 bv, 9 Wo, 10 bo
// ---------------------------------------------------------------------------
extern "C" void kernel_launch(void* const* d_in, const int* in_sizes, int n_in,
                              void* d_out, int out_size)
{
    const float* query = (const float*)d_in[0];
    const float* key   = (const float*)d_in[1];
    const float* Wq    = (const float*)d_in[3];
    const float* bq    = (const float*)d_in[4];
    const float* Wk    = (const float*)d_in[5];
    const float* bk    = (const float*)d_in[6];
    const float* Wv    = (const float*)d_in[7];
    const float* bv    = (const float*)d_in[8];
    const float* Wo    = (const float*)d_in[9];
    const float* bo    = (const float*)d_in[10];
    float* out = (float*)d_out;

    woeff_kernel<<<64, 512>>>(Wo);
    proj_kernel<<<dim3(BS / 64, 3), 256>>>(query, key, Wq, bq, Wk, bk, Wv, bv);
    attn_kernel<<<BB * NQT, 256>>>();
    outgemm_kernel<<<dim3(BS / 64, DD / 64), 256>>>(bo, out);
}

// round 2
// speedup vs baseline: 1.7076x; 1.7076x over previous
#include <cuda_runtime.h>
#include <cuda_bf16.h>
#include <cstdint>

// Problem constants
#define BB 4
#define SS 2048
#define DD 512
#define HH 8
#define DK 64
#define DV 64
#define BS (BB * SS)          // 8192 rows total
#define QTROWS 32             // query rows per attention block
#define NQT (SS / QTROWS)     // 64 q-tiles per batch

// Scratch (device globals: no allocations allowed)
__device__ float g_q[BS * DK];
__device__ float g_k[BS * DK];
__device__ float g_v[BS * DV];
__device__ float g_o[BS * DV];
__device__ float g_woeff[DV * DD];   // 64 x 512

// ---------------------------------------------------------------------------
// tf32 mma helpers
// ---------------------------------------------------------------------------
__device__ __forceinline__ unsigned f2tf(float f) {
    unsigned u;
    asm("cvt.rna.tf32.f32 %0, %1;" : "=r"(u) : "f"(f));
    return u;
}
__device__ __forceinline__ float f2tff(float f) {
    return __uint_as_float(f2tf(f));
}
// D(16x8,f32) += A(16x8,tf32,row) * B(8x8,tf32,col)
__device__ __forceinline__ void mma8(float* c, unsigned a0, unsigned a1,
                                     unsigned a2, unsigned a3,
                                     unsigned b0, unsigned b1) {
    asm volatile(
        "mma.sync.aligned.m16n8k8.row.col.f32.tf32.tf32.f32 "
        "{%0,%1,%2,%3}, {%4,%5,%6,%7}, {%8,%9}, {%0,%1,%2,%3};\n"
        : "+f"(c[0]), "+f"(c[1]), "+f"(c[2]), "+f"(c[3])
        : "r"(a0), "r"(a1), "r"(a2), "r"(a3), "r"(b0), "r"(b1));
}

// ---------------------------------------------------------------------------
// Kernel 1: fold Wo over identical heads: woeff[r,c] = sum_h Wo[h*64+r, c]
// ---------------------------------------------------------------------------
__global__ void woeff_kernel(const float* __restrict__ Wo) {
    int idx = blockIdx.x * blockDim.x + threadIdx.x;   // 64*512 = 32768
    if (idx < DV * DD) {
        int r = idx >> 9;          // /512
        int c = idx & 511;
        float s = 0.f;
#pragma unroll
        for (int h = 0; h < HH; ++h) s += Wo[((h << 6) + r) * DD + c];
        g_woeff[idx] = s;
    }
}

// ---------------------------------------------------------------------------
// Kernel 2: fused projections.  blockIdx.y: 0->q(query,Wq) 1->k(key,Wk) 2->v(key,Wv)
// C[8192,64] = A[8192,512] @ W[512,64] + b
// ---------------------------------------------------------------------------
__global__ void __launch_bounds__(256) proj_kernel(
    const float* __restrict__ query, const float* __restrict__ key,
    const float* __restrict__ Wq, const float* __restrict__ bq,
    const float* __restrict__ Wk, const float* __restrict__ bk,
    const float* __restrict__ Wv, const float* __restrict__ bv)
{
    const int which = blockIdx.y;
    const float* A    = (which == 0) ? query : key;
    const float* W    = (which == 0) ? Wq : (which == 1) ? Wk : Wv;
    const float* bias = (which == 0) ? bq : (which == 1) ? bk : bv;
    float* outp       = (which == 0) ? g_q : (which == 1) ? g_k : g_v;

    const int m0 = blockIdx.x * 64;
    __shared__ float As[64][33];
    __shared__ float Ws[32][64];

    const int t  = threadIdx.x;
    const int tr = t >> 4;
    const int tc = t & 15;

    float acc[4][4] = {};

    for (int kk = 0; kk < DD; kk += 32) {
        __syncthreads();
#pragma unroll
        for (int u = 0; u < 2; ++u) {
            int fi = t + u * 256;
            int r  = fi >> 3;
            int c4 = (fi & 7) << 2;
            float4 a4 = *(const float4*)(A + (size_t)(m0 + r) * DD + kk + c4);
            As[r][c4 + 0] = a4.x; As[r][c4 + 1] = a4.y;
            As[r][c4 + 2] = a4.z; As[r][c4 + 3] = a4.w;
        }
#pragma unroll
        for (int u = 0; u < 2; ++u) {
            int fi = t + u * 256;
            int r  = fi >> 4;
            int c4 = (fi & 15) << 2;
            *(float4*)&Ws[r][c4] = *(const float4*)(W + (size_t)(kk + r) * DK + c4);
        }
        __syncthreads();

#pragma unroll 8
        for (int k = 0; k < 32; ++k) {
            float a0 = As[(tr << 2) + 0][k];
            float a1 = As[(tr << 2) + 1][k];
            float a2 = As[(tr << 2) + 2][k];
            float a3 = As[(tr << 2) + 3][k];
            float4 b4 = *(const float4*)&Ws[k][tc << 2];
            acc[0][0] += a0 * b4.x; acc[0][1] += a0 * b4.y; acc[0][2] += a0 * b4.z; acc[0][3] += a0 * b4.w;
            acc[1][0] += a1 * b4.x; acc[1][1] += a1 * b4.y; acc[1][2] += a1 * b4.z; acc[1][3] += a1 * b4.w;
            acc[2][0] += a2 * b4.x; acc[2][1] += a2 * b4.y; acc[2][2] += a2 * b4.z; acc[2][3] += a2 * b4.w;
            acc[3][0] += a3 * b4.x; acc[3][1] += a3 * b4.y; acc[3][2] += a3 * b4.z; acc[3][3] += a3 * b4.w;
        }
    }

    float4 bb = *(const float4*)(bias + (tc << 2));
#pragma unroll
    for (int i = 0; i < 4; ++i) {
        float4 r4 = make_float4(acc[i][0] + bb.x, acc[i][1] + bb.y,
                                acc[i][2] + bb.z, acc[i][3] + bb.w);
        *(float4*)(outp + (size_t)(m0 + (tr << 2) + i) * DK + (tc << 2)) = r4;
    }
}

// ---------------------------------------------------------------------------
// Kernel 3: causal flash attention (one head) on tf32 tensor cores.
// Block = 32 q-rows, 128 threads = 4 warps.
// warp w: band = w>>1 (16-row band), ch = w&1 (32-key / 32-dim column half).
// S-tile 32x64 per KV tile; online softmax with cross-warp smem exchange.
// ---------------------------------------------------------------------------
__global__ void __launch_bounds__(128) attn_kernel() {
    const int b  = blockIdx.x & 3;
    const int it = (NQT - 1) - (blockIdx.x >> 2);   // longest-first

    __shared__ float kk[64][68];     // K tile, row-major [key][dim], pitch 68
    __shared__ float vv[64][72];     // V tile, row-major [key][dim], pitch 72
    __shared__ float sp[32][68];     // Q tile (prologue) then P tile [row][key]
    __shared__ float redm[2][32];    // per-colhalf row maxima
    __shared__ float redl[2][32];    // per-colhalf row sums

    const int t    = threadIdx.x;
    const int w    = t >> 5;
    const int lane = t & 31;
    const int band = w >> 1;     // 0..1
    const int ch   = w & 1;      // 0..1
    const int g    = lane >> 2;  // 0..7  (mma groupID)
    const int t4   = lane & 3;   // 0..3  (mma threadID_in_group)

    // ---- load Q tile (32x64) scaled by 1/sqrt(DK)=0.125, tf32-rounded ----
    const float* qg = g_q + (size_t)(b * SS + it * QTROWS) * DK;
#pragma unroll
    for (int u = 0; u < 4; ++u) {
        int fi = t + u * 128;        // 512 float4
        int r  = fi >> 4;
        int c4 = (fi & 15) << 2;
        float4 v4 = *(const float4*)(qg + r * DK + c4);
        sp[r][c4 + 0] = f2tff(v4.x * 0.125f);
        sp[r][c4 + 1] = f2tff(v4.y * 0.125f);
        sp[r][c4 + 2] = f2tff(v4.z * 0.125f);
        sp[r][c4 + 3] = f2tff(v4.w * 0.125f);
    }
    __syncthreads();

    // resident Q A-fragments: 8 k-tiles over dim
    unsigned aq[8][4];
#pragma unroll
    for (int kt = 0; kt < 8; ++kt) {
        aq[kt][0] = __float_as_uint(sp[band * 16 + g    ][kt * 8 + t4    ]);
        aq[kt][1] = __float_as_uint(sp[band * 16 + g + 8][kt * 8 + t4    ]);
        aq[kt][2] = __float_as_uint(sp[band * 16 + g    ][kt * 8 + t4 + 4]);
        aq[kt][3] = __float_as_uint(sp[band * 16 + g + 8][kt * 8 + t4 + 4]);
    }

    float o[4][4] = {};
    float mrow0 = -1e30f, mrow1 = -1e30f;
    float lrow0 = 0.f,    lrow1 = 0.f;

    const int ntiles = ((it * QTROWS + QTROWS - 1) >> 6) + 1;
    const float* kgp = g_k + (size_t)(b * SS) * DK;
    const float* vgp = g_v + (size_t)(b * SS) * DK;

    const int r0 = band * 16 + g;    // row index within q-tile (and +8)
    const int qpos0 = it * QTROWS + r0;

    for (int jt = 0; jt < ntiles; ++jt) {
        __syncthreads();   // prev iter's smem readers done
        // ---- load K,V tiles (64x64 each), tf32-rounded ----
#pragma unroll
        for (int u = 0; u < 8; ++u) {
            int fi = t + u * 128;    // 1024 float4
            int r  = fi >> 4;
            int c4 = (fi & 15) << 2;
            float4 a4 = *(const float4*)(kgp + (size_t)(jt * 64 + r) * DK + c4);
            kk[r][c4 + 0] = f2tff(a4.x);
            kk[r][c4 + 1] = f2tff(a4.y);
            kk[r][c4 + 2] = f2tff(a4.z);
            kk[r][c4 + 3] = f2tff(a4.w);
            float4 w4 = *(const float4*)(vgp + (size_t)(jt * 64 + r) * DK + c4);
            vv[r][c4 + 0] = f2tff(w4.x);
            vv[r][c4 + 1] = f2tff(w4.y);
            vv[r][c4 + 2] = f2tff(w4.z);
            vv[r][c4 + 3] = f2tff(w4.w);
        }
        __syncthreads();

        // ---- S = Q K^T (this warp: 16 rows x 32 keys) ----
        float c[4][4] = {};
#pragma unroll
        for (int kt = 0; kt < 8; ++kt) {
#pragma unroll
            for (int nt = 0; nt < 4; ++nt) {
                unsigned b0 = __float_as_uint(kk[ch * 32 + nt * 8 + g][kt * 8 + t4    ]);
                unsigned b1 = __float_as_uint(kk[ch * 32 + nt * 8 + g][kt * 8 + t4 + 4]);
                mma8(c[nt], aq[kt][0], aq[kt][1], aq[kt][2], aq[kt][3], b0, b1);
            }
        }

        // ---- causal mask (only last tile can be partial) ----
        if (jt == ntiles - 1) {
#pragma unroll
            for (int nt = 0; nt < 4; ++nt) {
                int kp = jt * 64 + ch * 32 + nt * 8 + 2 * t4;
                if (kp     > qpos0)     c[nt][0] = -1e30f;
                if (kp + 1 > qpos0)     c[nt][1] = -1e30f;
                if (kp     > qpos0 + 8) c[nt][2] = -1e30f;
                if (kp + 1 > qpos0 + 8) c[nt][3] = -1e30f;
            }
        }

        // ---- local row max over this warp's 32 keys ----
        float rm0 = -1e30f, rm1 = -1e30f;
#pragma unroll
        for (int nt = 0; nt < 4; ++nt) {
            rm0 = fmaxf(rm0, fmaxf(c[nt][0], c[nt][1]));
            rm1 = fmaxf(rm1, fmaxf(c[nt][2], c[nt][3]));
        }
        rm0 = fmaxf(rm0, __shfl_xor_sync(0xffffffffu, rm0, 1));
        rm0 = fmaxf(rm0, __shfl_xor_sync(0xffffffffu, rm0, 2));
        rm1 = fmaxf(rm1, __shfl_xor_sync(0xffffffffu, rm1, 1));
        rm1 = fmaxf(rm1, __shfl_xor_sync(0xffffffffu, rm1, 2));
        if (t4 == 0) {
            redm[ch][r0]     = rm0;
            redm[ch][r0 + 8] = rm1;
        }
        __syncthreads();

        // ---- combine maxima, exponentiate, local sums, store P ----
        float nm0 = fmaxf(mrow0, fmaxf(redm[0][r0],     redm[1][r0]));
        float nm1 = fmaxf(mrow1, fmaxf(redm[0][r0 + 8], redm[1][r0 + 8]));
        float corr0 = __expf(mrow0 - nm0); mrow0 = nm0;
        float corr1 = __expf(mrow1 - nm1); mrow1 = nm1;

        float rs0 = 0.f, rs1 = 0.f;
#pragma unroll
        for (int nt = 0; nt < 4; ++nt) {
            c[nt][0] = __expf(c[nt][0] - nm0);
            c[nt][1] = __expf(c[nt][1] - nm0);
            c[nt][2] = __expf(c[nt][2] - nm1);
            c[nt][3] = __expf(c[nt][3] - nm1);
            rs0 += c[nt][0] + c[nt][1];
            rs1 += c[nt][2] + c[nt][3];
        }
        rs0 += __shfl_xor_sync(0xffffffffu, rs0, 1);
        rs0 += __shfl_xor_sync(0xffffffffu, rs0, 2);
        rs1 += __shfl_xor_sync(0xffffffffu, rs1, 1);
        rs1 += __shfl_xor_sync(0xffffffffu, rs1, 2);
        if (t4 == 0) {
            redl[ch][r0]     = rs0;
            redl[ch][r0 + 8] = rs1;
        }
        // store P (tf32-rounded) into sp[row][key]
#pragma unroll
        for (int nt = 0; nt < 4; ++nt) {
            int kc = ch * 32 + nt * 8 + 2 * t4;
            *(float2*)&sp[r0][kc]     = make_float2(f2tff(c[nt][0]), f2tff(c[nt][1]));
            *(float2*)&sp[r0 + 8][kc] = make_float2(f2tff(c[nt][2]), f2tff(c[nt][3]));
        }
        // rescale O accumulators
#pragma unroll
        for (int nt = 0; nt < 4; ++nt) {
            o[nt][0] *= corr0; o[nt][1] *= corr0;
            o[nt][2] *= corr1; o[nt][3] *= corr1;
        }
        __syncthreads();
        lrow0 = lrow0 * corr0 + redl[0][r0]     + redl[1][r0];
        lrow1 = lrow1 * corr1 + redl[0][r0 + 8] + redl[1][r0 + 8];

        // ---- O += P V (this warp: 16 rows x 32 dims) ----
#pragma unroll
        for (int kt = 0; kt < 8; ++kt) {
            unsigned a0 = __float_as_uint(sp[r0    ][kt * 8 + t4    ]);
            unsigned a1 = __float_as_uint(sp[r0 + 8][kt * 8 + t4    ]);
            unsigned a2 = __float_as_uint(sp[r0    ][kt * 8 + t4 + 4]);
            unsigned a3 = __float_as_uint(sp[r0 + 8][kt * 8 + t4 + 4]);
#pragma unroll
            for (int nt = 0; nt < 4; ++nt) {
                unsigned b0 = __float_as_uint(vv[kt * 8 + t4    ][ch * 32 + nt * 8 + g]);
                unsigned b1 = __float_as_uint(vv[kt * 8 + t4 + 4][ch * 32 + nt * 8 + g]);
                mma8(o[nt], a0, a1, a2, a3, b0, b1);
            }
        }
    }

    // ---- epilogue: o = acc / l ----
    float inv0 = 1.f / lrow0;
    float inv1 = 1.f / lrow1;
    float* og = g_o + (size_t)(b * SS + it * QTROWS + band * 16) * DV + ch * 32;
#pragma unroll
    for (int nt = 0; nt < 4; ++nt) {
        int dc = nt * 8 + 2 * t4;
        *(float2*)(og + (size_t)g * DV + dc)       = make_float2(o[nt][0] * inv0, o[nt][1] * inv0);
        *(float2*)(og + (size_t)(g + 8) * DV + dc) = make_float2(o[nt][2] * inv1, o[nt][3] * inv1);
    }
}

// ---------------------------------------------------------------------------
// Kernel 4: out[8192,512] = o[8192,64] @ woeff[64,512] + bo
// ---------------------------------------------------------------------------
__global__ void __launch_bounds__(256) outgemm_kernel(
    const float* __restrict__ bo, float* __restrict__ out)
{
    const int m0 = blockIdx.x * 64;
    const int n0 = blockIdx.y * 64;
    __shared__ float Ao[64][65];
    __shared__ float Wt[64][64];

    const int t  = threadIdx.x;
    const int tr = t >> 4;
    const int tc = t & 15;

#pragma unroll
    for (int u = 0; u < 4; ++u) {
        int fi = t + u * 256;
        int r  = fi >> 4;
        int c4 = (fi & 15) << 2;
        float4 a4 = *(const float4*)(g_o + (size_t)(m0 + r) * DV + c4);
        Ao[r][c4 + 0] = a4.x; Ao[r][c4 + 1] = a4.y;
        Ao[r][c4 + 2] = a4.z; Ao[r][c4 + 3] = a4.w;
        *(float4*)&Wt[r][c4] = *(const float4*)(g_woeff + (size_t)r * DD + n0 + c4);
    }
    __syncthreads();

    float acc[4][4] = {};
#pragma unroll 8
    for (int k = 0; k < 64; ++k) {
        float a0 = Ao[(tr << 2) + 0][k];
        float a1 = Ao[(tr << 2) + 1][k];
        float a2 = Ao[(tr << 2) + 2][k];
        float a3 = Ao[(tr << 2) + 3][k];
        float4 b4 = *(const float4*)&Wt[k][tc << 2];
        acc[0][0] += a0 * b4.x; acc[0][1] += a0 * b4.y; acc[0][2] += a0 * b4.z; acc[0][3] += a0 * b4.w;
        acc[1][0] += a1 * b4.x; acc[1][1] += a1 * b4.y; acc[1][2] += a1 * b4.z; acc[1][3] += a1 * b4.w;
        acc[2][0] += a2 * b4.x; acc[2][1] += a2 * b4.y; acc[2][2] += a2 * b4.z; acc[2][3] += a2 * b4.w;
        acc[3][0] += a3 * b4.x; acc[3][1] += a3 * b4.y; acc[3][2] += a3 * b4.z; acc[3][3] += a3 * b4.w;
    }

    float4 bb = *(const float4*)(bo + n0 + (tc << 2));
#pragma unroll
    for (int i = 0; i < 4; ++i) {
        float4 r4 = make_float4(acc[i][0] + bb.x, acc[i][1] + bb.y,
                                acc[i][2] + bb.z, acc[i][3] + bb.w);
        *(float4*)(out + (size_t)(m0 + (tr << 2) + i) * DD + n0 + (tc << 2)) = r4;
    }
}

// ---------------------------------------------------------------------------
// Launch
// Inputs: 0 query, 1 key, 2 value(unused), 3 Wq, 4 bq, 5 Wk, 6 bk,
//         7 Wv, 8 bv, 9 Wo, 10 bo
// ---------------------------------------------------------------------------
extern "C" void kernel_launch(void* const* d_in, const int* in_sizes, int n_in,
                              void* d_out, int out_size)
{
    const float* query = (const float*)d_in[0];
    const float* key   = (const float*)d_in[1];
    const float* Wq    = (const float*)d_in[3];
    const float* bq    = (const float*)d_in[4];
    const float* Wk    = (const float*)d_in[5];
    const float* bk    = (const float*)d_in[6];
    const float* Wv    = (const float*)d_in[7];
    const float* bv    = (const float*)d_in[8];
    const float* Wo    = (const float*)d_in[9];
    const float* bo    = (const float*)d_in[10];
    float* out = (float*)d_out;

    woeff_kernel<<<64, 512>>>(Wo);
    proj_kernel<<<dim3(BS / 64, 3), 256>>>(query, key, Wq, bq, Wk, bk, Wv, bv);
    attn_kernel<<<BB * NQT, 128>>>();
    outgemm_kernel<<<dim3(BS / 64, DD / 64), 256>>>(bo, out);
}

// round 4
// speedup vs baseline: 2.2696x; 1.3291x over previous
#include <cuda_runtime.h>
#include <cuda_bf16.h>
#include <cstdint>

// Problem constants
#define BB 4
#define SS 2048
#define DD 512
#define HH 8
#define DK 64
#define DV 64
#define BS (BB * SS)          // 8192 rows total
#define QTROWS 32             // query rows per attention block
#define NQT (SS / QTROWS)     // 64 q-tiles per batch

// Scratch (device globals: no allocations allowed)
__device__ float g_q[BS * DK];
__device__ float g_k[BS * DK];
__device__ float g_v[BS * DV];
__device__ float g_o[BS * DV];
__device__ float g_woeff[DV * DD];   // 64 x 512

// ---------------------------------------------------------------------------
// tf32 mma helpers
// ---------------------------------------------------------------------------
__device__ __forceinline__ unsigned f2tf(float f) {
    unsigned u;
    asm("cvt.rna.tf32.f32 %0, %1;" : "=r"(u) : "f"(f));
    return u;
}
__device__ __forceinline__ float f2tff(float f) {
    return __uint_as_float(f2tf(f));
}
// D(16x8,f32) += A(16x8,tf32,row) * B(8x8,tf32,col)
__device__ __forceinline__ void mma8(float* c, unsigned a0, unsigned a1,
                                     unsigned a2, unsigned a3,
                                     unsigned b0, unsigned b1) {
    asm volatile(
        "mma.sync.aligned.m16n8k8.row.col.f32.tf32.tf32.f32 "
        "{%0,%1,%2,%3}, {%4,%5,%6,%7}, {%8,%9}, {%0,%1,%2,%3};\n"
        : "+f"(c[0]), "+f"(c[1]), "+f"(c[2]), "+f"(c[3])
        : "r"(a0), "r"(a1), "r"(a2), "r"(a3), "r"(b0), "r"(b1));
}

// ---------------------------------------------------------------------------
// Kernel 1: fold Wo over identical heads: woeff[r,c] = sum_h Wo[h*64+r, c]
// ---------------------------------------------------------------------------
__global__ void woeff_kernel(const float* __restrict__ Wo) {
    int idx = blockIdx.x * blockDim.x + threadIdx.x;   // 64*512 = 32768
    if (idx < DV * DD) {
        int r = idx >> 9;          // /512
        int c = idx & 511;
        float s = 0.f;
#pragma unroll
        for (int h = 0; h < HH; ++h) s += Wo[((h << 6) + r) * DD + c];
        g_woeff[idx] = s;
    }
}

// ---------------------------------------------------------------------------
// Kernel 2: fused projections on tf32 tensor cores.
// blockIdx.y: 0 -> q = query@Wq ; 1 -> k = key@Wk AND v = key@Wv (shared A tile)
// C[8192,64] = A[8192,512] @ W[512,64] + b
// 128 threads = 4 warps; warp w owns rows 16w..16w+15, all 64 cols.
// ---------------------------------------------------------------------------
__global__ void __launch_bounds__(128) proj_mma_kernel(
    const float* __restrict__ query, const float* __restrict__ key,
    const float* __restrict__ Wq, const float* __restrict__ bq,
    const float* __restrict__ Wk, const float* __restrict__ bk,
    const float* __restrict__ Wv, const float* __restrict__ bv)
{
    const int fused = blockIdx.y;           // 0: q, 1: k+v
    const float* A  = fused ? key : query;
    const int m0 = blockIdx.x * 64;

    __shared__ float As[64][36];    // A tile [row][k], pitch 36 -> bank 4g+t4
    __shared__ float W1s[32][72];   // W tile [k][n], pitch 72 -> bank 8t4+g
    __shared__ float W2s[32][72];

    const int t    = threadIdx.x;
    const int w    = t >> 5;
    const int lane = t & 31;
    const int g    = lane >> 2;
    const int t4   = lane & 3;

    float c1[8][4] = {};
    float c2[8][4] = {};

    for (int kk = 0; kk < DD; kk += 32) {
        __syncthreads();
        // A tile 64x32 (512 float4, 4 per thread), tf32-rounded
#pragma unroll
        for (int u = 0; u < 4; ++u) {
            int fi = t + u * 128;
            int r  = fi >> 3;
            int c4 = (fi & 7) << 2;
            float4 a4 = *(const float4*)(A + (size_t)(m0 + r) * DD + kk + c4);
            As[r][c4 + 0] = f2tff(a4.x);
            As[r][c4 + 1] = f2tff(a4.y);
            As[r][c4 + 2] = f2tff(a4.z);
            As[r][c4 + 3] = f2tff(a4.w);
        }
        // W tile(s) 32x64 (512 float4, 4 per thread each)
#pragma unroll
        for (int u = 0; u < 4; ++u) {
            int fi = t + u * 128;
            int r  = fi >> 4;
            int c4 = (fi & 15) << 2;
            const float* Wa = fused ? Wk : Wq;
            float4 w4 = *(const float4*)(Wa + (size_t)(kk + r) * DK + c4);
            W1s[r][c4 + 0] = f2tff(w4.x);
            W1s[r][c4 + 1] = f2tff(w4.y);
            W1s[r][c4 + 2] = f2tff(w4.z);
            W1s[r][c4 + 3] = f2tff(w4.w);
            if (fused) {
                float4 v4 = *(const float4*)(Wv + (size_t)(kk + r) * DK + c4);
                W2s[r][c4 + 0] = f2tff(v4.x);
                W2s[r][c4 + 1] = f2tff(v4.y);
                W2s[r][c4 + 2] = f2tff(v4.z);
                W2s[r][c4 + 3] = f2tff(v4.w);
            }
        }
        __syncthreads();

#pragma unroll
        for (int kt = 0; kt < 4; ++kt) {
            unsigned a0 = __float_as_uint(As[w * 16 + g    ][kt * 8 + t4    ]);
            unsigned a1 = __float_as_uint(As[w * 16 + g + 8][kt * 8 + t4    ]);
            unsigned a2 = __float_as_uint(As[w * 16 + g    ][kt * 8 + t4 + 4]);
            unsigned a3 = __float_as_uint(As[w * 16 + g + 8][kt * 8 + t4 + 4]);
#pragma unroll
            for (int nt = 0; nt < 8; ++nt) {
                unsigned b0 = __float_as_uint(W1s[kt * 8 + t4    ][nt * 8 + g]);
                unsigned b1 = __float_as_uint(W1s[kt * 8 + t4 + 4][nt * 8 + g]);
                mma8(c1[nt], a0, a1, a2, a3, b0, b1);
            }
            if (fused) {
#pragma unroll
                for (int nt = 0; nt < 8; ++nt) {
                    unsigned b0 = __float_as_uint(W2s[kt * 8 + t4    ][nt * 8 + g]);
                    unsigned b1 = __float_as_uint(W2s[kt * 8 + t4 + 4][nt * 8 + g]);
                    mma8(c2[nt], a0, a1, a2, a3, b0, b1);
                }
            }
        }
    }

    // epilogue
    const int r0 = m0 + w * 16 + g;
    const float* bias1 = fused ? bk : bq;
    float* out1        = fused ? g_k : g_q;
#pragma unroll
    for (int nt = 0; nt < 8; ++nt) {
        int cc = nt * 8 + 2 * t4;
        float b0 = bias1[cc], b1 = bias1[cc + 1];
        *(float2*)(out1 + (size_t)r0 * DK + cc)       = make_float2(c1[nt][0] + b0, c1[nt][1] + b1);
        *(float2*)(out1 + (size_t)(r0 + 8) * DK + cc) = make_float2(c1[nt][2] + b0, c1[nt][3] + b1);
    }
    if (fused) {
#pragma unroll
        for (int nt = 0; nt < 8; ++nt) {
            int cc = nt * 8 + 2 * t4;
            float b0 = bv[cc], b1 = bv[cc + 1];
            *(float2*)(g_v + (size_t)r0 * DK + cc)       = make_float2(c2[nt][0] + b0, c2[nt][1] + b1);
            *(float2*)(g_v + (size_t)(r0 + 8) * DK + cc) = make_float2(c2[nt][2] + b0, c2[nt][3] + b1);
        }
    }
}

// ---------------------------------------------------------------------------
// Kernel 3: causal flash attention (one head) on tf32 tensor cores.
// Block = 32 q-rows, 128 threads = 4 warps.
// warp w: band = w>>1 (16-row band), ch = w&1 (32-key / 32-dim column half).
// ---------------------------------------------------------------------------
__global__ void __launch_bounds__(128) attn_kernel() {
    const int b  = blockIdx.x & 3;
    const int it = (NQT - 1) - (blockIdx.x >> 2);   // longest-first

    __shared__ float kk[64][68];     // K tile [key][dim], pitch 68
    __shared__ float vv[64][72];     // V tile [key][dim], pitch 72
    __shared__ float sp[32][68];     // Q tile (prologue) then P tile [row][key]
    __shared__ float redm[2][32];
    __shared__ float redl[2][32];

    const int t    = threadIdx.x;
    const int w    = t >> 5;
    const int lane = t & 31;
    const int band = w >> 1;
    const int ch   = w & 1;
    const int g    = lane >> 2;
    const int t4   = lane & 3;

    const float* qg = g_q + (size_t)(b * SS + it * QTROWS) * DK;
#pragma unroll
    for (int u = 0; u < 4; ++u) {
        int fi = t + u * 128;
        int r  = fi >> 4;
        int c4 = (fi & 15) << 2;
        float4 v4 = *(const float4*)(qg + r * DK + c4);
        sp[r][c4 + 0] = f2tff(v4.x * 0.125f);
        sp[r][c4 + 1] = f2tff(v4.y * 0.125f);
        sp[r][c4 + 2] = f2tff(v4.z * 0.125f);
        sp[r][c4 + 3] = f2tff(v4.w * 0.125f);
    }
    __syncthreads();

    unsigned aq[8][4];
#pragma unroll
    for (int kt = 0; kt < 8; ++kt) {
        aq[kt][0] = __float_as_uint(sp[band * 16 + g    ][kt * 8 + t4    ]);
        aq[kt][1] = __float_as_uint(sp[band * 16 + g + 8][kt * 8 + t4    ]);
        aq[kt][2] = __float_as_uint(sp[band * 16 + g    ][kt * 8 + t4 + 4]);
        aq[kt][3] = __float_as_uint(sp[band * 16 + g + 8][kt * 8 + t4 + 4]);
    }

    float o[4][4] = {};
    float mrow0 = -1e30f, mrow1 = -1e30f;
    float lrow0 = 0.f,    lrow1 = 0.f;

    const int ntiles = ((it * QTROWS + QTROWS - 1) >> 6) + 1;
    const float* kgp = g_k + (size_t)(b * SS) * DK;
    const float* vgp = g_v + (size_t)(b * SS) * DK;

    const int r0 = band * 16 + g;
    const int qpos0 = it * QTROWS + r0;

    for (int jt = 0; jt < ntiles; ++jt) {
        __syncthreads();
#pragma unroll
        for (int u = 0; u < 8; ++u) {
            int fi = t + u * 128;
            int r  = fi >> 4;
            int c4 = (fi & 15) << 2;
            float4 a4 = *(const float4*)(kgp + (size_t)(jt * 64 + r) * DK + c4);
            kk[r][c4 + 0] = f2tff(a4.x);
            kk[r][c4 + 1] = f2tff(a4.y);
            kk[r][c4 + 2] = f2tff(a4.z);
            kk[r][c4 + 3] = f2tff(a4.w);
            float4 w4 = *(const float4*)(vgp + (size_t)(jt * 64 + r) * DK + c4);
            vv[r][c4 + 0] = f2tff(w4.x);
            vv[r][c4 + 1] = f2tff(w4.y);
            vv[r][c4 + 2] = f2tff(w4.z);
            vv[r][c4 + 3] = f2tff(w4.w);
        }
        __syncthreads();

        float c[4][4] = {};
#pragma unroll
        for (int kt = 0; kt < 8; ++kt) {
#pragma unroll
            for (int nt = 0; nt < 4; ++nt) {
                unsigned b0 = __float_as_uint(kk[ch * 32 + nt * 8 + g][kt * 8 + t4    ]);
                unsigned b1 = __float_as_uint(kk[ch * 32 + nt * 8 + g][kt * 8 + t4 + 4]);
                mma8(c[nt], aq[kt][0], aq[kt][1], aq[kt][2], aq[kt][3], b0, b1);
            }
        }

        if (jt == ntiles - 1) {
#pragma unroll
            for (int nt = 0; nt < 4; ++nt) {
                int kp = jt * 64 + ch * 32 + nt * 8 + 2 * t4;
                if (kp     > qpos0)     c[nt][0] = -1e30f;
                if (kp + 1 > qpos0)     c[nt][1] = -1e30f;
                if (kp     > qpos0 + 8) c[nt][2] = -1e30f;
                if (kp + 1 > qpos0 + 8) c[nt][3] = -1e30f;
            }
        }

        float rm0 = -1e30f, rm1 = -1e30f;
#pragma unroll
        for (int nt = 0; nt < 4; ++nt) {
            rm0 = fmaxf(rm0, fmaxf(c[nt][0], c[nt][1]));
            rm1 = fmaxf(rm1, fmaxf(c[nt][2], c[nt][3]));
        }
        rm0 = fmaxf(rm0, __shfl_xor_sync(0xffffffffu, rm0, 1));
        rm0 = fmaxf(rm0, __shfl_xor_sync(0xffffffffu, rm0, 2));
        rm1 = fmaxf(rm1, __shfl_xor_sync(0xffffffffu, rm1, 1));
        rm1 = fmaxf(rm1, __shfl_xor_sync(0xffffffffu, rm1, 2));
        if (t4 == 0) {
            redm[ch][r0]     = rm0;
            redm[ch][r0 + 8] = rm1;
        }
        __syncthreads();

        float nm0 = fmaxf(mrow0, fmaxf(redm[0][r0],     redm[1][r0]));
        float nm1 = fmaxf(mrow1, fmaxf(redm[0][r0 + 8], redm[1][r0 + 8]));
        float corr0 = __expf(mrow0 - nm0); mrow0 = nm0;
        float corr1 = __expf(mrow1 - nm1); mrow1 = nm1;

        float rs0 = 0.f, rs1 = 0.f;
#pragma unroll
        for (int nt = 0; nt < 4; ++nt) {
            c[nt][0] = __expf(c[nt][0] - nm0);
            c[nt][1] = __expf(c[nt][1] - nm0);
            c[nt][2] = __expf(c[nt][2] - nm1);
            c[nt][3] = __expf(c[nt][3] - nm1);
            rs0 += c[nt][0] + c[nt][1];
            rs1 += c[nt][2] + c[nt][3];
        }
        rs0 += __shfl_xor_sync(0xffffffffu, rs0, 1);
        rs0 += __shfl_xor_sync(0xffffffffu, rs0, 2);
        rs1 += __shfl_xor_sync(0xffffffffu, rs1, 1);
        rs1 += __shfl_xor_sync(0xffffffffu, rs1, 2);
        if (t4 == 0) {
            redl[ch][r0]     = rs0;
            redl[ch][r0 + 8] = rs1;
        }
#pragma unroll
        for (int nt = 0; nt < 4; ++nt) {
            int kc = ch * 32 + nt * 8 + 2 * t4;
            *(float2*)&sp[r0][kc]     = make_float2(f2tff(c[nt][0]), f2tff(c[nt][1]));
            *(float2*)&sp[r0 + 8][kc] = make_float2(f2tff(c[nt][2]), f2tff(c[nt][3]));
        }
#pragma unroll
        for (int nt = 0; nt < 4; ++nt) {
            o[nt][0] *= corr0; o[nt][1] *= corr0;
            o[nt][2] *= corr1; o[nt][3] *= corr1;
        }
        __syncthreads();
        lrow0 = lrow0 * corr0 + redl[0][r0]     + redl[1][r0];
        lrow1 = lrow1 * corr1 + redl[0][r0 + 8] + redl[1][r0 + 8];

#pragma unroll
        for (int kt = 0; kt < 8; ++kt) {
            unsigned a0 = __float_as_uint(sp[r0    ][kt * 8 + t4    ]);
            unsigned a1 = __float_as_uint(sp[r0 + 8][kt * 8 + t4    ]);
            unsigned a2 = __float_as_uint(sp[r0    ][kt * 8 + t4 + 4]);
            unsigned a3 = __float_as_uint(sp[r0 + 8][kt * 8 + t4 + 4]);
#pragma unroll
            for (int nt = 0; nt < 4; ++nt) {
                unsigned b0 = __float_as_uint(vv[kt * 8 + t4    ][ch * 32 + nt * 8 + g]);
                unsigned b1 = __float_as_uint(vv[kt * 8 + t4 + 4][ch * 32 + nt * 8 + g]);
                mma8(o[nt], a0, a1, a2, a3, b0, b1);
            }
        }
    }

    float inv0 = 1.f / lrow0;
    float inv1 = 1.f / lrow1;
    float* og = g_o + (size_t)(b * SS + it * QTROWS + band * 16) * DV + ch * 32;
#pragma unroll
    for (int nt = 0; nt < 4; ++nt) {
        int dc = nt * 8 + 2 * t4;
        *(float2*)(og + (size_t)g * DV + dc)       = make_float2(o[nt][0] * inv0, o[nt][1] * inv0);
        *(float2*)(og + (size_t)(g + 8) * DV + dc) = make_float2(o[nt][2] * inv1, o[nt][3] * inv1);
    }
}

// ---------------------------------------------------------------------------
// Kernel 4: out[8192,512] = o[8192,64] @ woeff[64,512] + bo  (tf32 mma)
// 128 threads = 4 warps; block = 64 rows x 64 cols; K = 64 single shot.
// warp w: rows 16w..16w+15, all 64 cols.
// ---------------------------------------------------------------------------
__global__ void __launch_bounds__(128) outgemm_mma_kernel(
    const float* __restrict__ bo, float* __restrict__ out)
{
    const int m0 = blockIdx.x * 64;
    const int n0 = blockIdx.y * 64;

    __shared__ float Ao[64][68];     // o tile [row][k], pitch 68 -> bank 4g+t4
    __shared__ float Ws[64][72];     // woeff tile [k][n], pitch 72 -> bank 8t4+g

    const int t    = threadIdx.x;
    const int w    = t >> 5;
    const int lane = t & 31;
    const int g    = lane >> 2;
    const int t4   = lane & 3;

    // load o tile 64x64 and woeff tile 64x64 (1024 float4 each, 8 per thread)
#pragma unroll
    for (int u = 0; u < 8; ++u) {
        int fi = t + u * 128;
        int r  = fi >> 4;
        int c4 = (fi & 15) << 2;
        float4 a4 = *(const float4*)(g_o + (size_t)(m0 + r) * DV + c4);
        Ao[r][c4 + 0] = f2tff(a4.x);
        Ao[r][c4 + 1] = f2tff(a4.y);
        Ao[r][c4 + 2] = f2tff(a4.z);
        Ao[r][c4 + 3] = f2tff(a4.w);
        float4 w4 = *(const float4*)(g_woeff + (size_t)r * DD + n0 + c4);
        Ws[r][c4 + 0] = f2tff(w4.x);
        Ws[r][c4 + 1] = f2tff(w4.y);
        Ws[r][c4 + 2] = f2tff(w4.z);
        Ws[r][c4 + 3] = f2tff(w4.w);
    }
    __syncthreads();

    float c[8][4] = {};
#pragma unroll
    for (int kt = 0; kt < 8; ++kt) {
        unsigned a0 = __float_as_uint(Ao[w * 16 + g    ][kt * 8 + t4    ]);
        unsigned a1 = __float_as_uint(Ao[w * 16 + g + 8][kt * 8 + t4    ]);
        unsigned a2 = __float_as_uint(Ao[w * 16 + g    ][kt * 8 + t4 + 4]);
        unsigned a3 = __float_as_uint(Ao[w * 16 + g + 8][kt * 8 + t4 + 4]);
#pragma unroll
        for (int nt = 0; nt < 8; ++nt) {
            unsigned b0 = __float_as_uint(Ws[kt * 8 + t4    ][nt * 8 + g]);
            unsigned b1 = __float_as_uint(Ws[kt * 8 + t4 + 4][nt * 8 + g]);
            mma8(c[nt], a0, a1, a2, a3, b0, b1);
        }
    }

    const int row0 = m0 + w * 16 + g;
#pragma unroll
    for (int nt = 0; nt < 8; ++nt) {
        int cc = n0 + nt * 8 + 2 * t4;
        float b0 = bo[cc], b1 = bo[cc + 1];
        *(float2*)(out + (size_t)row0 * DD + cc)       = make_float2(c[nt][0] + b0, c[nt][1] + b1);
        *(float2*)(out + (size_t)(row0 + 8) * DD + cc) = make_float2(c[nt][2] + b0, c[nt][3] + b1);
    }
}

// ---------------------------------------------------------------------------
// Launch
// Inputs: 0 query, 1 key, 2 value(unused), 3 Wq, 4 bq, 5 Wk, 6 bk,
//         7 Wv, 8 bv, 9 Wo, 10 bo
// ---------------------------------------------------------------------------
extern "C" void kernel_launch(void* const* d_in, const int* in_sizes, int n_in,
                              void* d_out, int out_size)
{
    const float* query = (const float*)d_in[0];
    const float* key   = (const float*)d_in[1];
    const float* Wq    = (const float*)d_in[3];
    const float* bq    = (const float*)d_in[4];
    const float* Wk    = (const float*)d_in[5];
    const float* bk    = (const float*)d_in[6];
    const float* Wv    = (const float*)d_in[7];
    const float* bv    = (const float*)d_in[8];
    const float* Wo    = (const float*)d_in[9];
    const float* bo    = (const float*)d_in[10];
    float* out = (float*)d_out;

    woeff_kernel<<<64, 512>>>(Wo);
    proj_mma_kernel<<<dim3(BS / 64, 2), 128>>>(query, key, Wq, bq, Wk, bk, Wv, bv);
    attn_kernel<<<BB * NQT, 128>>>();
    outgemm_mma_kernel<<<dim3(BS / 64, DD / 64), 128>>>(bo, out);
}